// round 5
// baseline (speedup 1.0000x reference)
#include <cuda_runtime.h>
#include <cuda_bf16.h>

// Global accumulator + completion ticket. Zero-initialized; the last CTA of
// each launch resets them so CUDA-graph replays are deterministic.
__device__ float        g_accum = 0.0f;
__device__ unsigned int g_count = 0u;

// One CTA per segment, 128 threads — identical streaming body to the ~15.2us
// R1/R4 kernel. Fused finalize with NO gpu-scope fence (no CCTL.IVALL):
//   relaxed REDG accum  ->  release-atomic ticket  ->  (last CTA) acquire load.
__global__ __launch_bounds__(128) void listnet_fused_kernel(
    const float* __restrict__ mean,
    const float* __restrict__ variance,
    const float* __restrict__ targets,
    const int*   __restrict__ scope,
    float* __restrict__ out,
    int seg_len, int num_seg)
{
    const int seg = blockIdx.x;
    const int tid = threadIdx.x;           // 0..127
    const long long base = (long long)seg * seg_len;

    const float4* __restrict__ m4 = reinterpret_cast<const float4*>(mean + base);
    const float4* __restrict__ v4 = reinterpret_cast<const float4*>(variance + base);
    const float4* __restrict__ t4 = reinterpret_cast<const float4*>(targets + base);

    float s1 = 0.0f;  // sum exp(a),  a = x + 0.5 y
    float s2 = 0.0f;  // sum exp(t)
    float s3 = 0.0f;  // sum exp(t) * b,  b = x - 0.5 y

    const int nvec = seg_len >> 2;         // float4s per segment (128 for 512)
    for (int i = tid; i < nvec; i += 128) {
        float4 m = __ldg(&m4[i]);
        float4 v = __ldg(&v4[i]);
        float4 t = __ldg(&t4[i]);

        { float h = 0.5f * v.x; float a = m.x + h, b = m.x - h;
          float ea = __expf(a), et = __expf(t.x);
          s1 += ea; s2 += et; s3 += et * b; }
        { float h = 0.5f * v.y; float a = m.y + h, b = m.y - h;
          float ea = __expf(a), et = __expf(t.y);
          s1 += ea; s2 += et; s3 += et * b; }
        { float h = 0.5f * v.z; float a = m.z + h, b = m.z - h;
          float ea = __expf(a), et = __expf(t.z);
          s1 += ea; s2 += et; s3 += et * b; }
        { float h = 0.5f * v.w; float a = m.w + h, b = m.w - h;
          float ea = __expf(a), et = __expf(t.w);
          s1 += ea; s2 += et; s3 += et * b; }
    }

    // Warp reduction (3 values)
    #pragma unroll
    for (int off = 16; off > 0; off >>= 1) {
        s1 += __shfl_down_sync(0xFFFFFFFFu, s1, off);
        s2 += __shfl_down_sync(0xFFFFFFFFu, s2, off);
        s3 += __shfl_down_sync(0xFFFFFFFFu, s3, off);
    }

    __shared__ float sh1[4], sh2[4], sh3[4];
    const int warp = tid >> 5;
    const int lane = tid & 31;
    if (lane == 0) { sh1[warp] = s1; sh2[warp] = s2; sh3[warp] = s3; }
    __syncthreads();

    if (tid == 0) {
        float S1 = sh1[0] + sh1[1] + sh1[2] + sh1[3];
        float S2 = sh2[0] + sh2[1] + sh2[2] + sh2[3];
        float S3 = sh3[0] + sh3[1] + sh3[2] + sh3[3];
        // per_seg = (log(S1) - S3/S2) / scope[seg]
        float val = (logf(S1) - S3 / S2) / (float)scope[seg];

        // 1) Relaxed accumulate (REDG, no fence).
        atomicAdd(&g_accum, val);

        // 2) Release-scope ticket: orders the accum-add above before this
        //    ticket becomes visible. Write-side only — no L1D invalidate.
        unsigned int old;
        asm volatile("atom.add.release.gpu.u32 %0, [%1], 1;"
                     : "=r"(old) : "l"(&g_count) : "memory");

        // 3) Last CTA: acquire-load the accumulator (executed once chip-wide),
        //    finalize, and reset the globals for the next graph replay.
        if (old == (unsigned int)num_seg - 1u) {
            float acc;
            asm volatile("ld.acquire.gpu.f32 %0, [%1];"
                         : "=f"(acc) : "l"(&g_accum) : "memory");
            out[0] = acc / (float)num_seg;
            g_accum = 0.0f;
            g_count = 0u;
        }
    }
}

extern "C" void kernel_launch(void* const* d_in, const int* in_sizes, int n_in,
                              void* d_out, int out_size)
{
    // metadata order: mean (N), variance (N), scope (NUM_SEG), targets (N)
    const float* mean     = (const float*)d_in[0];
    const float* variance = (const float*)d_in[1];
    const int*   scope    = (const int*)  d_in[2];
    const float* targets  = (const float*)d_in[3];
    float* out = (float*)d_out;

    const int n       = in_sizes[0];
    const int num_seg = in_sizes[2];
    const int seg_len = n / num_seg;   // 512 for this dataset

    listnet_fused_kernel<<<num_seg, 128>>>(mean, variance, targets, scope, out,
                                           seg_len, num_seg);
}

// round 6
// speedup vs baseline: 1.0136x; 1.0136x over previous
#include <cuda_runtime.h>
#include <cuda_bf16.h>

// Global accumulator + completion ticket. Zero-initialized; the last CTA of
// each launch resets them so CUDA-graph replays are deterministic.
__device__ float        g_accum = 0.0f;
__device__ unsigned int g_count = 0u;

// One CTA per segment, 128 threads. __launch_bounds__(128, 16) forces the
// register allocation back to 32 regs (16 CTAs/SM) — the fused-tail versions
// at 40 regs dropped to 12 CTAs/SM and halved the streaming bandwidth.
__global__ __launch_bounds__(128, 16) void listnet_fused_kernel(
    const float* __restrict__ mean,
    const float* __restrict__ variance,
    const float* __restrict__ targets,
    const int*   __restrict__ scope,
    float* __restrict__ out,
    int seg_len, int num_seg)
{
    const int seg = blockIdx.x;
    const int tid = threadIdx.x;           // 0..127
    const long long base = (long long)seg * seg_len;

    const float4* __restrict__ m4 = reinterpret_cast<const float4*>(mean + base);
    const float4* __restrict__ v4 = reinterpret_cast<const float4*>(variance + base);
    const float4* __restrict__ t4 = reinterpret_cast<const float4*>(targets + base);

    float s1 = 0.0f;  // sum exp(a),  a = x + 0.5 y
    float s2 = 0.0f;  // sum exp(t)
    float s3 = 0.0f;  // sum exp(t) * b,  b = x - 0.5 y

    const int nvec = seg_len >> 2;         // float4s per segment (128 for 512)
    for (int i = tid; i < nvec; i += 128) {
        float4 m = __ldg(&m4[i]);
        float4 v = __ldg(&v4[i]);
        float4 t = __ldg(&t4[i]);

        { float h = 0.5f * v.x; float a = m.x + h, b = m.x - h;
          float ea = __expf(a), et = __expf(t.x);
          s1 += ea; s2 += et; s3 += et * b; }
        { float h = 0.5f * v.y; float a = m.y + h, b = m.y - h;
          float ea = __expf(a), et = __expf(t.y);
          s1 += ea; s2 += et; s3 += et * b; }
        { float h = 0.5f * v.z; float a = m.z + h, b = m.z - h;
          float ea = __expf(a), et = __expf(t.z);
          s1 += ea; s2 += et; s3 += et * b; }
        { float h = 0.5f * v.w; float a = m.w + h, b = m.w - h;
          float ea = __expf(a), et = __expf(t.w);
          s1 += ea; s2 += et; s3 += et * b; }
    }

    // Warp reduction (3 values)
    #pragma unroll
    for (int off = 16; off > 0; off >>= 1) {
        s1 += __shfl_down_sync(0xFFFFFFFFu, s1, off);
        s2 += __shfl_down_sync(0xFFFFFFFFu, s2, off);
        s3 += __shfl_down_sync(0xFFFFFFFFu, s3, off);
    }

    __shared__ float sh1[4], sh2[4], sh3[4];
    const int warp = tid >> 5;
    const int lane = tid & 31;
    if (lane == 0) { sh1[warp] = s1; sh2[warp] = s2; sh3[warp] = s3; }
    __syncthreads();

    if (tid == 0) {
        float S1 = sh1[0] + sh1[1] + sh1[2] + sh1[3];
        float S2 = sh2[0] + sh2[1] + sh2[2] + sh2[3];
        float S3 = sh3[0] + sh3[1] + sh3[2] + sh3[3];
        // per_seg = (log(S1) - S3/S2) / scope[seg]
        float val = (logf(S1) - S3 / S2) / (float)scope[seg];

        // 1) Relaxed accumulate (REDG, no fence).
        atomicAdd(&g_accum, val);

        // 2) Release-scope ticket: orders the accum-add above before this
        //    ticket becomes visible. Write-side only — no L1D invalidate.
        unsigned int old;
        asm volatile("atom.add.release.gpu.u32 %0, [%1], 1;"
                     : "=r"(old) : "l"(&g_count) : "memory");

        // 3) Last CTA: acquire-load the accumulator (executed once chip-wide),
        //    finalize, and reset the globals for the next graph replay.
        if (old == (unsigned int)num_seg - 1u) {
            float acc;
            asm volatile("ld.acquire.gpu.f32 %0, [%1];"
                         : "=f"(acc) : "l"(&g_accum) : "memory");
            out[0] = acc / (float)num_seg;
            g_accum = 0.0f;
            g_count = 0u;
        }
    }
}

extern "C" void kernel_launch(void* const* d_in, const int* in_sizes, int n_in,
                              void* d_out, int out_size)
{
    // metadata order: mean (N), variance (N), scope (NUM_SEG), targets (N)
    const float* mean     = (const float*)d_in[0];
    const float* variance = (const float*)d_in[1];
    const int*   scope    = (const int*)  d_in[2];
    const float* targets  = (const float*)d_in[3];
    float* out = (float*)d_out;

    const int n       = in_sizes[0];
    const int num_seg = in_sizes[2];
    const int seg_len = n / num_seg;   // 512 for this dataset

    listnet_fused_kernel<<<num_seg, 128>>>(mean, variance, targets, scope, out,
                                           seg_len, num_seg);
}

// round 7
// speedup vs baseline: 1.4710x; 1.4512x over previous
#include <cuda_runtime.h>
#include <cuda_bf16.h>

// Global accumulator + completion ticket. Zero-initialized; the last CTA of
// each launch resets them so CUDA-graph replays are deterministic.
__device__ float        g_accum = 0.0f;
__device__ unsigned int g_count = 0u;

#define GRID_CTAS 2048

// Persistent-ish: 2048 CTAs x 128 threads; each CTA serially processes
// num_seg/2048 segments (8 for this dataset), accumulating the per-segment
// losses in a tid0 register. ONE atomic round-trip per ~8000-cycle CTA
// lifetime, so the blocking retirement tail is amortized to noise.
__global__ __launch_bounds__(128, 16) void listnet_fused_kernel(
    const float* __restrict__ mean,
    const float* __restrict__ variance,
    const float* __restrict__ targets,
    const int*   __restrict__ scope,
    float* __restrict__ out,
    int seg_len, int num_seg)
{
    const int tid  = threadIdx.x;          // 0..127
    const int warp = tid >> 5;
    const int lane = tid & 31;
    const int nvec = seg_len >> 2;         // float4s per segment (128 for 512)

    // Double-buffered per-warp partials: [parity][s1/s2/s3][warp]
    __shared__ float sh[2][3][4];

    float cta_sum = 0.0f;                  // meaningful on tid0 only
    int par = 0;

    for (int seg = blockIdx.x; seg < num_seg; seg += GRID_CTAS) {
        const long long base = (long long)seg * seg_len;
        const float4* __restrict__ m4 = reinterpret_cast<const float4*>(mean + base);
        const float4* __restrict__ v4 = reinterpret_cast<const float4*>(variance + base);
        const float4* __restrict__ t4 = reinterpret_cast<const float4*>(targets + base);

        float s1 = 0.0f;  // sum exp(a),  a = x + 0.5 y
        float s2 = 0.0f;  // sum exp(t)
        float s3 = 0.0f;  // sum exp(t) * b,  b = x - 0.5 y

        for (int i = tid; i < nvec; i += 128) {
            float4 m = m4[i];
            float4 v = v4[i];
            float4 t = t4[i];

            { float h = 0.5f * v.x; float a = m.x + h, b = m.x - h;
              float ea = __expf(a), et = __expf(t.x);
              s1 += ea; s2 += et; s3 += et * b; }
            { float h = 0.5f * v.y; float a = m.y + h, b = m.y - h;
              float ea = __expf(a), et = __expf(t.y);
              s1 += ea; s2 += et; s3 += et * b; }
            { float h = 0.5f * v.z; float a = m.z + h, b = m.z - h;
              float ea = __expf(a), et = __expf(t.z);
              s1 += ea; s2 += et; s3 += et * b; }
            { float h = 0.5f * v.w; float a = m.w + h, b = m.w - h;
              float ea = __expf(a), et = __expf(t.w);
              s1 += ea; s2 += et; s3 += et * b; }
        }

        // Warp-level reduce (3 values)
        #pragma unroll
        for (int off = 16; off > 0; off >>= 1) {
            s1 += __shfl_down_sync(0xFFFFFFFFu, s1, off);
            s2 += __shfl_down_sync(0xFFFFFFFFu, s2, off);
            s3 += __shfl_down_sync(0xFFFFFFFFu, s3, off);
        }

        if (lane == 0) {
            sh[par][0][warp] = s1;
            sh[par][1][warp] = s2;
            sh[par][2][warp] = s3;
        }
        __syncthreads();   // one sync per segment; parity buffer makes reuse safe

        if (tid == 0) {
            float S1 = sh[par][0][0] + sh[par][0][1] + sh[par][0][2] + sh[par][0][3];
            float S2 = sh[par][1][0] + sh[par][1][1] + sh[par][1][2] + sh[par][1][3];
            float S3 = sh[par][2][0] + sh[par][2][1] + sh[par][2][2] + sh[par][2][3];
            // per_seg = (log(S1) - S3/S2) / scope[seg]
            cta_sum += (logf(S1) - S3 / S2) / (float)scope[seg];
        }
        par ^= 1;
    }

    if (tid == 0) {
        // 1) Relaxed accumulate (fire-and-forget REDG).
        atomicAdd(&g_accum, cta_sum);

        // 2) Release-scope ticket: orders the accum-add before the ticket.
        unsigned int old;
        asm volatile("atom.add.release.gpu.u32 %0, [%1], 1;"
                     : "=r"(old) : "l"(&g_count) : "memory");

        // 3) Last CTA finalizes and resets for the next graph replay.
        if (old == (unsigned int)GRID_CTAS - 1u) {
            float acc;
            asm volatile("ld.acquire.gpu.f32 %0, [%1];"
                         : "=f"(acc) : "l"(&g_accum) : "memory");
            out[0] = acc / (float)num_seg;
            g_accum = 0.0f;
            g_count = 0u;
        }
    }
}

extern "C" void kernel_launch(void* const* d_in, const int* in_sizes, int n_in,
                              void* d_out, int out_size)
{
    // metadata order: mean (N), variance (N), scope (NUM_SEG), targets (N)
    const float* mean     = (const float*)d_in[0];
    const float* variance = (const float*)d_in[1];
    const int*   scope    = (const int*)  d_in[2];
    const float* targets  = (const float*)d_in[3];
    float* out = (float*)d_out;

    const int n       = in_sizes[0];
    const int num_seg = in_sizes[2];
    const int seg_len = n / num_seg;   // 512 for this dataset

    listnet_fused_kernel<<<GRID_CTAS, 128>>>(mean, variance, targets, scope, out,
                                             seg_len, num_seg);
}

// round 8
// speedup vs baseline: 1.9697x; 1.3390x over previous
#include <cuda_runtime.h>
#include <cuda_bf16.h>

// Global accumulator + completion ticket. Zero-initialized; the last CTA of
// each launch resets them so CUDA-graph replays are deterministic.
__device__ float        g_accum = 0.0f;
__device__ unsigned int g_count = 0u;

#define GRID_CTAS 2048
#define VEC_PER_LANE 4   // 32 lanes * 4 float4 = 128 float4 = 512 floats/segment

// Warp-per-segment: each warp streams whole segments with 12 batched LDG.128
// (MLP=12) and reduces via shuffles only — NO __syncthreads() in the hot path.
// One atomic per CTA at the very end.
__global__ __launch_bounds__(128) void listnet_fused_kernel(
    const float* __restrict__ mean,
    const float* __restrict__ variance,
    const float* __restrict__ targets,
    const int*   __restrict__ scope,
    float* __restrict__ out,
    int seg_len, int num_seg)
{
    const int tid   = threadIdx.x;          // 0..127
    const int warp  = tid >> 5;             // 0..3
    const int lane  = tid & 31;
    const int gwarp = blockIdx.x * 4 + warp;         // global warp id
    const int nwarp = GRID_CTAS * 4;                  // total warps

    float warp_sum = 0.0f;                  // meaningful on lane 0 only

    for (int seg = gwarp; seg < num_seg; seg += nwarp) {
        const long long base = (long long)seg * seg_len;
        const float4* __restrict__ m4 = reinterpret_cast<const float4*>(mean + base);
        const float4* __restrict__ v4 = reinterpret_cast<const float4*>(variance + base);
        const float4* __restrict__ t4 = reinterpret_cast<const float4*>(targets + base);

        // Batch all loads up front: 12 independent LDG.128 per lane.
        float4 m[VEC_PER_LANE], v[VEC_PER_LANE], t[VEC_PER_LANE];
        #pragma unroll
        for (int j = 0; j < VEC_PER_LANE; j++) {
            int i = lane + j * 32;          // coalesced: consecutive lanes -> consecutive vec4
            m[j] = m4[i];
            v[j] = v4[i];
            t[j] = t4[i];
        }

        float s1 = 0.0f;  // sum exp(a),  a = x + 0.5 y
        float s2 = 0.0f;  // sum exp(t)
        float s3 = 0.0f;  // sum exp(t) * b,  b = x - 0.5 y

        #pragma unroll
        for (int j = 0; j < VEC_PER_LANE; j++) {
            { float h = 0.5f * v[j].x; float a = m[j].x + h, b = m[j].x - h;
              float ea = __expf(a), et = __expf(t[j].x);
              s1 += ea; s2 += et; s3 += et * b; }
            { float h = 0.5f * v[j].y; float a = m[j].y + h, b = m[j].y - h;
              float ea = __expf(a), et = __expf(t[j].y);
              s1 += ea; s2 += et; s3 += et * b; }
            { float h = 0.5f * v[j].z; float a = m[j].z + h, b = m[j].z - h;
              float ea = __expf(a), et = __expf(t[j].z);
              s1 += ea; s2 += et; s3 += et * b; }
            { float h = 0.5f * v[j].w; float a = m[j].w + h, b = m[j].w - h;
              float ea = __expf(a), et = __expf(t[j].w);
              s1 += ea; s2 += et; s3 += et * b; }
        }

        // Warp-level reduce of (s1, s2, s3) — shuffles only, no barrier.
        #pragma unroll
        for (int off = 16; off > 0; off >>= 1) {
            s1 += __shfl_down_sync(0xFFFFFFFFu, s1, off);
            s2 += __shfl_down_sync(0xFFFFFFFFu, s2, off);
            s3 += __shfl_down_sync(0xFFFFFFFFu, s3, off);
        }

        if (lane == 0) {
            // per_seg = (log(S1) - S3/S2) / scope[seg]
            warp_sum += (logf(s1) - s3 / s2) / (float)scope[seg];
        }
    }

    // CTA combine: 4 warp sums -> one value, then ONE atomic per CTA.
    __shared__ float sh[4];
    if (lane == 0) sh[warp] = warp_sum;
    __syncthreads();

    if (tid == 0) {
        float cta_sum = sh[0] + sh[1] + sh[2] + sh[3];

        // 1) Relaxed accumulate (fire-and-forget REDG).
        atomicAdd(&g_accum, cta_sum);

        // 2) Release-scope ticket: orders the accum-add before the ticket.
        unsigned int old;
        asm volatile("atom.add.release.gpu.u32 %0, [%1], 1;"
                     : "=r"(old) : "l"(&g_count) : "memory");

        // 3) Last CTA finalizes and resets for the next graph replay.
        if (old == (unsigned int)GRID_CTAS - 1u) {
            float acc;
            asm volatile("ld.acquire.gpu.f32 %0, [%1];"
                         : "=f"(acc) : "l"(&g_accum) : "memory");
            out[0] = acc / (float)num_seg;
            g_accum = 0.0f;
            g_count = 0u;
        }
    }
}

extern "C" void kernel_launch(void* const* d_in, const int* in_sizes, int n_in,
                              void* d_out, int out_size)
{
    // metadata order: mean (N), variance (N), scope (NUM_SEG), targets (N)
    const float* mean     = (const float*)d_in[0];
    const float* variance = (const float*)d_in[1];
    const int*   scope    = (const int*)  d_in[2];
    const float* targets  = (const float*)d_in[3];
    float* out = (float*)d_out;

    const int n       = in_sizes[0];
    const int num_seg = in_sizes[2];
    const int seg_len = n / num_seg;   // 512 for this dataset

    listnet_fused_kernel<<<GRID_CTAS, 128>>>(mean, variance, targets, scope, out,
                                             seg_len, num_seg);
}

// round 9
// speedup vs baseline: 1.9923x; 1.0115x over previous
#include <cuda_runtime.h>
#include <cuda_bf16.h>

// Global accumulator + completion ticket. Zero-initialized; the last CTA of
// each launch resets them so CUDA-graph replays are deterministic.
__device__ float        g_accum = 0.0f;
__device__ unsigned int g_count = 0u;

#define GRID_CTAS 2048
#define VEC_PER_LANE 4   // 32 lanes * 4 float4 = 128 float4 = 512 floats/segment

// Fold one (m, v, t) float4 triple into the three running sums.
__device__ __forceinline__ void fold4(const float4& m, const float4& v,
                                      const float4& t,
                                      float& s1, float& s2, float& s3)
{
    { float h = 0.5f * v.x; float a = m.x + h, b = m.x - h;
      float ea = __expf(a), et = __expf(t.x);
      s1 += ea; s2 += et; s3 += et * b; }
    { float h = 0.5f * v.y; float a = m.y + h, b = m.y - h;
      float ea = __expf(a), et = __expf(t.y);
      s1 += ea; s2 += et; s3 += et * b; }
    { float h = 0.5f * v.z; float a = m.z + h, b = m.z - h;
      float ea = __expf(a), et = __expf(t.z);
      s1 += ea; s2 += et; s3 += et * b; }
    { float h = 0.5f * v.w; float a = m.w + h, b = m.w - h;
      float ea = __expf(a), et = __expf(t.w);
      s1 += ea; s2 += et; s3 += et * b; }
}

// Warp-per-2-contiguous-segments, software-pipelined:
//   load A -> fold A -> load B -> fold B -> (deferred, interleaved) reduce A+B.
// No __syncthreads() in the hot path; no shuffle chain between the load waves.
__global__ __launch_bounds__(128) void listnet_fused_kernel(
    const float* __restrict__ mean,
    const float* __restrict__ variance,
    const float* __restrict__ targets,
    const int*   __restrict__ scope,
    float* __restrict__ out,
    int seg_len, int num_seg)
{
    const int tid   = threadIdx.x;          // 0..127
    const int warp  = tid >> 5;             // 0..3
    const int lane  = tid & 31;
    const int gwarp = blockIdx.x * 4 + warp;          // global warp id
    const int nwarp = GRID_CTAS * 4;                  // total warps (8192)

    float warp_sum = 0.0f;                  // meaningful on lane 0 only

    // Each warp owns 2 contiguous segments per outer iteration.
    for (int segA = gwarp * 2; segA < num_seg; segA += nwarp * 2) {
        const int segB = segA + 1;
        const bool hasB = (segB < num_seg);

        const long long baseA = (long long)segA * seg_len;
        const float4* __restrict__ mA = reinterpret_cast<const float4*>(mean + baseA);
        const float4* __restrict__ vA = reinterpret_cast<const float4*>(variance + baseA);
        const float4* __restrict__ tA = reinterpret_cast<const float4*>(targets + baseA);

        float s1a = 0.0f, s2a = 0.0f, s3a = 0.0f;
        float s1b = 0.0f, s2b = 0.0f, s3b = 0.0f;

        // ---- Segment A: batch 12 LDG.128, then fold (no reduce yet) ----
        {
            float4 m[VEC_PER_LANE], v[VEC_PER_LANE], t[VEC_PER_LANE];
            #pragma unroll
            for (int j = 0; j < VEC_PER_LANE; j++) {
                int i = lane + j * 32;
                m[j] = mA[i]; v[j] = vA[i]; t[j] = tA[i];
            }
            #pragma unroll
            for (int j = 0; j < VEC_PER_LANE; j++)
                fold4(m[j], v[j], t[j], s1a, s2a, s3a);
        }

        // ---- Segment B: loads issue immediately (independent of A's sums) ----
        if (hasB) {
            const float4* __restrict__ mB = mA + (seg_len >> 2);
            const float4* __restrict__ vB = vA + (seg_len >> 2);
            const float4* __restrict__ tB = tA + (seg_len >> 2);
            float4 m[VEC_PER_LANE], v[VEC_PER_LANE], t[VEC_PER_LANE];
            #pragma unroll
            for (int j = 0; j < VEC_PER_LANE; j++) {
                int i = lane + j * 32;
                m[j] = mB[i]; v[j] = vB[i]; t[j] = tB[i];
            }
            #pragma unroll
            for (int j = 0; j < VEC_PER_LANE; j++)
                fold4(m[j], v[j], t[j], s1b, s2b, s3b);
        }

        // ---- Deferred, interleaved reductions: 6 independent shuffle chains ----
        #pragma unroll
        for (int off = 16; off > 0; off >>= 1) {
            s1a += __shfl_down_sync(0xFFFFFFFFu, s1a, off);
            s2a += __shfl_down_sync(0xFFFFFFFFu, s2a, off);
            s3a += __shfl_down_sync(0xFFFFFFFFu, s3a, off);
            s1b += __shfl_down_sync(0xFFFFFFFFu, s1b, off);
            s2b += __shfl_down_sync(0xFFFFFFFFu, s2b, off);
            s3b += __shfl_down_sync(0xFFFFFFFFu, s3b, off);
        }

        if (lane == 0) {
            // per_seg = (log(S1) - S3/S2) / scope[seg]
            warp_sum += (__logf(s1a) - s3a / s2a) / (float)scope[segA];
            if (hasB)
                warp_sum += (__logf(s1b) - s3b / s2b) / (float)scope[segB];
        }
    }

    // CTA combine: 4 warp sums -> one value, then ONE atomic per CTA.
    __shared__ float sh[4];
    if (lane == 0) sh[warp] = warp_sum;
    __syncthreads();

    if (tid == 0) {
        float cta_sum = sh[0] + sh[1] + sh[2] + sh[3];

        // 1) Relaxed accumulate (fire-and-forget REDG).
        atomicAdd(&g_accum, cta_sum);

        // 2) Release-scope ticket: orders the accum-add before the ticket.
        unsigned int old;
        asm volatile("atom.add.release.gpu.u32 %0, [%1], 1;"
                     : "=r"(old) : "l"(&g_count) : "memory");

        // 3) Last CTA finalizes and resets for the next graph replay.
        if (old == (unsigned int)GRID_CTAS - 1u) {
            float acc;
            asm volatile("ld.acquire.gpu.f32 %0, [%1];"
                         : "=f"(acc) : "l"(&g_accum) : "memory");
            out[0] = acc / (float)num_seg;
            g_accum = 0.0f;
            g_count = 0u;
        }
    }
}

extern "C" void kernel_launch(void* const* d_in, const int* in_sizes, int n_in,
                              void* d_out, int out_size)
{
    // metadata order: mean (N), variance (N), scope (NUM_SEG), targets (N)
    const float* mean     = (const float*)d_in[0];
    const float* variance = (const float*)d_in[1];
    const int*   scope    = (const int*)  d_in[2];
    const float* targets  = (const float*)d_in[3];
    float* out = (float*)d_out;

    const int n       = in_sizes[0];
    const int num_seg = in_sizes[2];
    const int seg_len = n / num_seg;   // 512 for this dataset

    listnet_fused_kernel<<<GRID_CTAS, 128>>>(mean, variance, targets, scope, out,
                                             seg_len, num_seg);
}